// round 15
// baseline (speedup 1.0000x reference)
#include <cuda_runtime.h>
#include <stdint.h>

// Wavelet denoising: 3-level Haar DWT, soft-threshold (exact median of |cd1|),
// inverse DWT. Rows of L=1024, warp-per-row, cyclic float4 layout.
//
// R15: grid-stride loop over rows (each warp handles ~8 rows) with software
// prefetch — the next row's 8x LDG.128 are issued as soon as the current row's
// raw data has been folded into level-1/2 coefficients, so the load latency
// hides behind the median search + inverse transform. Transform is
// unnormalized (scales folded into thresholds / final FMAs); median is EXACT.

__global__ __launch_bounds__(256) void wavelet_rows_kernel(
    const float* __restrict__ x, float* __restrict__ out, int nrows)
{
    const int warp = threadIdx.x >> 5;
    const int lane = threadIdx.x & 31;
    const int warps_total = gridDim.x * 8;
    int row = blockIdx.x * 8 + warp;
    if (row >= nrows) return;

    const float4* __restrict__ xb = reinterpret_cast<const float4*>(x);
    float4* __restrict__ ob       = reinterpret_cast<float4*>(out);

    // initial load
    float4 v[8];
    {
        const float4* xr = xb + (size_t)row * 256;
#pragma unroll
        for (int i = 0; i < 8; i++) v[i] = __ldcs(&xr[i * 32 + lane]);
    }

    while (true) {
        const int nxt = row + warps_total;

        // ---- levels 1+2, unnormalized (consumes v) ----
        float cd1[16], ca2[8], cd2[8];
#pragma unroll
        for (int i = 0; i < 8; i++) {
            float a = v[i].x + v[i].y;
            cd1[2*i]   = v[i].x - v[i].y;
            float b = v[i].z + v[i].w;
            cd1[2*i+1] = v[i].z - v[i].w;
            ca2[i] = a + b;
            cd2[i] = a - b;
        }

        // ---- prefetch next row (v is dead now; hides behind median loop) ----
        if (nxt < nrows) {
            const float4* xn = xb + (size_t)nxt * 256;
#pragma unroll
            for (int i = 0; i < 8; i++) v[i] = __ldcs(&xn[i * 32 + lane]);
        }

        // ---- level 3 (adjacent-lane pairs; valid in even lanes) ----
        float ca3[8], cd3[8];
#pragma unroll
        for (int i = 0; i < 8; i++) {
            float nb = __shfl_down_sync(0xffffffffu, ca2[i], 1);
            ca3[i] = ca2[i] + nb;
            cd3[i] = ca2[i] - nb;
        }

        // ============ exact median of |cd1'| (512 values, warp-wide) ==========
        float s = 0.f;
#pragma unroll
        for (int i = 0; i < 16; i++) s += fabsf(cd1[i]);
#pragma unroll
        for (int d = 16; d; d >>= 1) s += __shfl_xor_sync(0xffffffffu, s, d);
        const float m_est = s * 0.0016511f;          // 0.84536/512
        const float stepk = m_est * 0.0045548f;      // sigma/(512*f_med)

        unsigned lo = 0u, hi = 0x7f800000u;          // cnt(lo)=0, cnt(+inf)=512
        int nlo = 0, nhi = 512;
        const int R = 255;
        float s255;
        float pnewton = m_est;
        int it = 0;
        while (true) {
            if (nlo == R) {
                unsigned mb = 0x7f800000u;
#pragma unroll
                for (int i = 0; i < 16; i++) {
                    unsigned ua = __float_as_uint(cd1[i]) & 0x7fffffffu;
                    if (ua >= lo) mb = min(mb, ua);
                }
                s255 = __uint_as_float(__reduce_min_sync(0xffffffffu, mb));
                break;
            }
            if (nhi == R + 1) {
                unsigned mb = 0u;
#pragma unroll
                for (int i = 0; i < 16; i++) {
                    unsigned ua = __float_as_uint(cd1[i]) & 0x7fffffffu;
                    if (ua < hi) mb = max(mb, ua);
                }
                s255 = __uint_as_float(__reduce_max_sync(0xffffffffu, mb));
                break;
            }
            if (hi - lo <= 1u) { s255 = __uint_as_float(lo); break; }

            unsigned p;
            if (it < 8) p = __float_as_uint(fmaxf(pnewton, 0.0f));
            else        p = lo + ((hi - lo) >> 1);   // safeguard bisection
            if (p <= lo) p = lo + 1u;
            if (p >= hi) p = hi - 1u;
            const float pf = __uint_as_float(p);

            float fc = 0.f;
#pragma unroll
            for (int i = 0; i < 16; i++) fc += (float)(fabsf(cd1[i]) < pf);
            const int c = (int)__reduce_add_sync(0xffffffffu, (unsigned)fc);
            if (c <= R) { lo = p; nlo = c; } else { hi = p; nhi = c; }
            pnewton = fmaf(255.5f - (float)c, stepk, pf);
            it++;
        }

        // rank 256
        float fle = 0.f;
#pragma unroll
        for (int i = 0; i < 16; i++) fle += (float)(fabsf(cd1[i]) <= s255);
        const int cle = (int)__reduce_add_sync(0xffffffffu, (unsigned)fle);
        float s256;
        if (cle >= 257) {
            s256 = s255;
        } else {
            const unsigned sb = __float_as_uint(s255);
            unsigned mb = 0x7f800000u;
#pragma unroll
            for (int i = 0; i < 16; i++) {
                unsigned ua = __float_as_uint(cd1[i]) & 0x7fffffffu;
                if (ua > sb) mb = min(mb, ua);
            }
            s256 = __uint_as_float(__reduce_min_sync(0xffffffffu, mb));
        }

        const float median = 0.5f * (s255 + s256) * 0.70710678118654752440f;
        const float lamda  = (median / 0.6745f) * 3.7232974f;
        const float t1h = lamda * 0.70710678f;   // 0.5*(lamda)/C
        const float t2p = lamda * 1.26185951f;   // (lamda/log2(3))/C^2
        const float t3p = lamda * 1.41421356f;   // (lamda*0.5)/C^3

        // ---- inverse level 3 (primed domain) ----
        float u[8];
#pragma unroll
        for (int i = 0; i < 8; i++) {
            float a3 = fabsf(cd3[i]);
            float s3 = copysignf(fmaxf(a3 - t3p, 0.0f), cd3[i]);
            float e = ca3[i] + s3;
            float o = ca3[i] - s3;
            float up = __shfl_up_sync(0xffffffffu, o, 1);
            u[i] = (lane & 1) ? up : e;
        }

        // ---- inverse level 2 + level 1 + store ----
        float4* outr = ob + (size_t)row * 256;
#pragma unroll
        for (int i = 0; i < 8; i++) {
            float a2 = fabsf(cd2[i]);
            float s2 = copysignf(fmaxf(a2 - t2p, 0.0f), cd2[i]);
            float va = fmaf(u[i], 0.5f,  s2);
            float vb = fmaf(u[i], 0.5f, -s2);
            float s1a = copysignf(fmaxf(fmaf(fabsf(cd1[2*i]),   0.5f, -t1h), 0.0f), cd1[2*i]);
            float s1b = copysignf(fmaxf(fmaf(fabsf(cd1[2*i+1]), 0.5f, -t1h), 0.0f), cd1[2*i+1]);
            float4 w;
            w.x = fmaf(va, 0.25f,  s1a);
            w.y = fmaf(va, 0.25f, -s1a);
            w.z = fmaf(vb, 0.25f,  s1b);
            w.w = fmaf(vb, 0.25f, -s1b);
            __stcs(&outr[i * 32 + lane], w);
        }

        if (nxt >= nrows) break;
        row = nxt;
    }
}

extern "C" void kernel_launch(void* const* d_in, const int* in_sizes, int n_in,
                              void* d_out, int out_size)
{
    const float* x = (const float*)d_in[0];
    float* out = (float*)d_out;
    int n = in_sizes[0];
    int nrows = n >> 10;                 // L = 1024 per row
    // ~8 rows per warp: 1024 CTAs x 8 warps = 8192 warps for 65536 rows
    int blocks = (nrows + 63) / 64;
    if (blocks < 1) blocks = 1;
    wavelet_rows_kernel<<<blocks, 256>>>(x, out, nrows);
}

// round 16
// speedup vs baseline: 1.0787x; 1.0787x over previous
#include <cuda_runtime.h>
#include <stdint.h>

// Wavelet denoising: 3-level Haar DWT, soft-threshold (exact median of |cd1|),
// inverse DWT. Rows of L=1024, warp-per-row, cyclic float4 layout.
//
// R16: R14 structure (no cross-row prefetch — that regressed via register
// pressure), but the 24 floats that are dead during the median search
// (cd2[8], ca3[8], cd3[8]) are parked in shared memory, cutting live
// registers so 5 CTAs/SM fit (62.5% theoretical occupancy). More resident
// warps -> more concurrent LDG bursts -> higher DRAM duty cycle.

__global__ __launch_bounds__(256, 5) void wavelet_rows_kernel(
    const float* __restrict__ x, float* __restrict__ out, int nrows)
{
    // per-warp park buffer: [warp][coeff][lane], lane-major -> conflict-free
    __shared__ float park[8][24][32];

    const int warp = threadIdx.x >> 5;
    const int lane = threadIdx.x & 31;
    const int row  = blockIdx.x * 8 + warp;
    if (row >= nrows) return;

    const float4* __restrict__ xr = reinterpret_cast<const float4*>(x) + (size_t)row * 256;
    float4* __restrict__ outr     = reinterpret_cast<float4*>(out)     + (size_t)row * 256;

    // ---- forward, UNNORMALIZED (plain sums/differences) ----
    float cd1[16];
#pragma unroll
    for (int i = 0; i < 8; i++) {
        float4 v = __ldcs(&xr[i * 32 + lane]);
        float a = v.x + v.y;
        cd1[2*i]   = v.x - v.y;
        float b = v.z + v.w;
        cd1[2*i+1] = v.z - v.w;
        float ca2 = a + b;          // level 2
        float cd2 = a - b;
        float nb = __shfl_down_sync(0xffffffffu, ca2, 1);   // level 3 (even lanes)
        park[warp][i][lane]      = cd2;
        park[warp][8 + i][lane]  = ca2 + nb;   // ca3
        park[warp][16 + i][lane] = ca2 - nb;   // cd3
    }

    // ============ exact median of |cd1'| (512 values, warp-wide) ==========
    // Seed: median(half-normal) ~= 0.84536*mean. Newton pivots on empirical CDF;
    // exact termination via count==255 / count==256 passes.
    float s = 0.f;
#pragma unroll
    for (int i = 0; i < 16; i++) s += fabsf(cd1[i]);
#pragma unroll
    for (int d = 16; d; d >>= 1) s += __shfl_xor_sync(0xffffffffu, s, d);
    const float m_est = s * 0.0016511f;          // 0.84536/512
    const float stepk = m_est * 0.0045548f;      // sigma/(512*f_med)

    unsigned lo = 0u, hi = 0x7f800000u;          // cnt(lo)=0, cnt(+inf)=512
    int nlo = 0, nhi = 512;
    const int R = 255;
    float s255;
    float pnewton = m_est;
    int it = 0;
    while (true) {
        if (nlo == R) {
            unsigned mb = 0x7f800000u;
#pragma unroll
            for (int i = 0; i < 16; i++) {
                unsigned ua = __float_as_uint(cd1[i]) & 0x7fffffffu;
                if (ua >= lo) mb = min(mb, ua);
            }
            s255 = __uint_as_float(__reduce_min_sync(0xffffffffu, mb));
            break;
        }
        if (nhi == R + 1) {
            unsigned mb = 0u;
#pragma unroll
            for (int i = 0; i < 16; i++) {
                unsigned ua = __float_as_uint(cd1[i]) & 0x7fffffffu;
                if (ua < hi) mb = max(mb, ua);
            }
            s255 = __uint_as_float(__reduce_max_sync(0xffffffffu, mb));
            break;
        }
        if (hi - lo <= 1u) { s255 = __uint_as_float(lo); break; }

        unsigned p;
        if (it < 8) p = __float_as_uint(fmaxf(pnewton, 0.0f));
        else        p = lo + ((hi - lo) >> 1);   // safeguard bisection
        if (p <= lo) p = lo + 1u;
        if (p >= hi) p = hi - 1u;
        const float pf = __uint_as_float(p);

        float fc = 0.f;
#pragma unroll
        for (int i = 0; i < 16; i++) fc += (float)(fabsf(cd1[i]) < pf);
        const int c = (int)__reduce_add_sync(0xffffffffu, (unsigned)fc);
        if (c <= R) { lo = p; nlo = c; } else { hi = p; nhi = c; }
        pnewton = fmaf(255.5f - (float)c, stepk, pf);
        it++;
    }

    // rank 256
    float fle = 0.f;
#pragma unroll
    for (int i = 0; i < 16; i++) fle += (float)(fabsf(cd1[i]) <= s255);
    const int cle = (int)__reduce_add_sync(0xffffffffu, (unsigned)fle);
    float s256;
    if (cle >= 257) {
        s256 = s255;
    } else {
        const unsigned sb = __float_as_uint(s255);
        unsigned mb = 0x7f800000u;
#pragma unroll
        for (int i = 0; i < 16; i++) {
            unsigned ua = __float_as_uint(cd1[i]) & 0x7fffffffu;
            if (ua > sb) mb = min(mb, ua);
        }
        s256 = __uint_as_float(__reduce_min_sync(0xffffffffu, mb));
    }

    // thresholds (true scale), folded into primed (unnormalized) domain
    const float median = 0.5f * (s255 + s256) * 0.70710678118654752440f;
    const float lamda  = (median / 0.6745f) * 3.7232974f;
    const float t1h = lamda * 0.70710678f;   // 0.5*(lamda)/C
    const float t2p = lamda * 1.26185951f;   // (lamda/log2(3))/C^2
    const float t3p = lamda * 1.41421356f;   // (lamda*0.5)/C^3

    // ---- inverse: unpark + reconstruct + store, one chunk at a time ----
#pragma unroll
    for (int i = 0; i < 8; i++) {
        float cd2 = park[warp][i][lane];
        float ca3 = park[warp][8 + i][lane];
        float cd3 = park[warp][16 + i][lane];

        // inverse level 3 (primed domain): u = ca2r'/... via adjacent lanes
        float s3 = copysignf(fmaxf(fabsf(cd3) - t3p, 0.0f), cd3);
        float e = ca3 + s3;
        float o = ca3 - s3;
        float up = __shfl_up_sync(0xffffffffu, o, 1);
        float u = (lane & 1) ? up : e;

        // inverse level 2
        float s2 = copysignf(fmaxf(fabsf(cd2) - t2p, 0.0f), cd2);
        float va = fmaf(u, 0.5f,  s2);
        float vb = fmaf(u, 0.5f, -s2);

        // inverse level 1 + store
        float s1a = copysignf(fmaxf(fmaf(fabsf(cd1[2*i]),   0.5f, -t1h), 0.0f), cd1[2*i]);
        float s1b = copysignf(fmaxf(fmaf(fabsf(cd1[2*i+1]), 0.5f, -t1h), 0.0f), cd1[2*i+1]);
        float4 w;
        w.x = fmaf(va, 0.25f,  s1a);
        w.y = fmaf(va, 0.25f, -s1a);
        w.z = fmaf(vb, 0.25f,  s1b);
        w.w = fmaf(vb, 0.25f, -s1b);
        __stcs(&outr[i * 32 + lane], w);
    }
}

extern "C" void kernel_launch(void* const* d_in, const int* in_sizes, int n_in,
                              void* d_out, int out_size)
{
    const float* x = (const float*)d_in[0];
    float* out = (float*)d_out;
    int n = in_sizes[0];
    int nrows = n >> 10;                 // L = 1024 per row
    int blocks = (nrows + 7) / 8;        // 8 rows (warps) per 256-thread CTA
    wavelet_rows_kernel<<<blocks, 256>>>(x, out, nrows);
}